// round 13
// baseline (speedup 1.0000x reference)
#include <cuda_runtime.h>
#include <cuda_fp16.h>
#include <cstdint>

// ---------------- problem constants ----------------
#define BB 2
#define SS 1024
#define TT (BB*SS)      // 2048 tokens
#define HID 2880
#define HQ 64
#define HKV 8
#define DD 64
#define GG (HQ/HKV)     // 8
#define WW 128
#define QSZ (HQ*DD)     // 4096
#define KVSZ (HKV*DD)   // 512
#define QKVSZ (QSZ + 2*KVSZ)  // 5120
#define SCALE 0.125f
#define THETA 150000.0f
#define WSCALE 64.0f
#define OSCALE (1.0f/64.0f)

// ---------------- scratch (no allocation allowed) ----------------
__device__ __half g_hs_hi[TT*HID];
__device__ __half g_Wqkv_hi[QKVSZ*HID];   // [n][k] K-major, combined q|k|v order
__device__ float  g_bqkv[QKVSZ];
__device__ float  g_qkv[TT*QKVSZ];        // q | k | v per token
__device__ __half g_Wo_hi[HID*QSZ];       // [n=HID][k=QSZ]
__device__ __half g_att_hi[TT*QSZ];

// ---------------- low-level helpers ----------------
__device__ __forceinline__ uint32_t smem_u32(const void* p) {
    uint32_t a;
    asm("{ .reg .u64 t; cvta.to.shared.u64 t, %1; cvt.u32.u64 %0, t; }" : "=r"(a) : "l"(p));
    return a;
}

__device__ __forceinline__ void cp_async16(uint32_t dst, const void* src, bool valid) {
    int sz = valid ? 16 : 0;
    asm volatile("cp.async.cg.shared.global [%0], [%1], 16, %2;"
                 :: "r"(dst), "l"(src), "r"(sz));
}
#define CP_COMMIT asm volatile("cp.async.commit_group;")
template<int NN> __device__ __forceinline__ void cp_wait() {
    asm volatile("cp.async.wait_group %0;" :: "n"(NN));
}

__device__ __forceinline__ void ldsm_x4(uint32_t r[4], uint32_t addr) {
    asm volatile("ldmatrix.sync.aligned.m8n8.x4.shared.b16 {%0,%1,%2,%3}, [%4];"
        : "=r"(r[0]), "=r"(r[1]), "=r"(r[2]), "=r"(r[3]) : "r"(addr));
}

__device__ __forceinline__ void mma_f16(float c[4], const uint32_t a[4],
                                        uint32_t b0, uint32_t b1) {
    asm volatile(
        "mma.sync.aligned.m16n8k16.row.col.f32.f16.f16.f32 "
        "{%0,%1,%2,%3}, {%4,%5,%6,%7}, {%8,%9}, {%0,%1,%2,%3};"
        : "+f"(c[0]), "+f"(c[1]), "+f"(c[2]), "+f"(c[3])
        : "r"(a[0]), "r"(a[1]), "r"(a[2]), "r"(a[3]), "r"(b0), "r"(b1));
}

// ---------------- fp16 single-pass GEMM, BK=64, 128 threads ----------------
// C[M,N] = (Ah[M,K] @ BTh[N,K]^T) * oscale + bias.
// CTA tile 128x128, BK=64, 128 threads / 4 warps, warp tile 64x64.
// Per kt: 8 LDSM feed 32 independent MMAs; 256-reg budget (128thr x 2 CTA).
// Per stage (32KB): [Ah 16K | Bh 16K], 4 ktiles each. 3 stages.
// Chunk layout: region*16384 + kt*4096 + (r>>4)*512 + cs*16,
//   cs = (h*16 + r%16) ^ ((4*kt + 2*h) & 7).
#define BK 64
#define STG1_BYTES 32768
#define GEMM1_SMEM (3*STG1_BYTES + 128)

__global__ __launch_bounds__(128, 2) void gemm_f16single(
    const __half* __restrict__ Ah, const __half* __restrict__ Bh,
    const float* __restrict__ bias, float* __restrict__ C,
    int M, int N, int K, float oscale)
{
    extern __shared__ char raw[];
    const uint32_t base = (smem_u32(raw) + 127u) & ~127u;

    const int tid  = threadIdx.x;
    const int warp = tid >> 5, lane = tid & 31;
    const int bm = blockIdx.y * 128;
    const int bn = blockIdx.x * 128;
    const int wm = (warp >> 1) * 64;
    const int wn = (warp & 1) * 64;
    const int wmt = wm >> 4;    // 0 or 4
    const int wnt = wn >> 4;    // 0 or 4

    float acc[4][8][4];
    #pragma unroll
    for (int i = 0; i < 4; i++)
        #pragma unroll
        for (int j = 0; j < 8; j++)
            #pragma unroll
            for (int c = 0; c < 4; c++) acc[i][j][c] = 0.f;

    // ldmatrix lane offsets: kt even -> xor 2h, kt odd -> xor (4+2h)
    uint32_t lsw[2];
    {
        int h = lane >> 4;
        lsw[0] = (uint32_t)((lane ^ ((2 * h) & 7)) * 16);
        lsw[1] = (uint32_t)((lane ^ ((4 + 2 * h) & 7)) * 16);
    }

    const int NB = K / BK;

    auto issue = [&](int s, int k0) {
        uint32_t stg = base + (uint32_t)s * STG1_BYTES;
        #pragma unroll
        for (int i = 0; i < 16; i++) {
            int region = i >> 3;            // 0 A, 1 B
            int idx = tid + (i & 7) * 128;  // 0..1023
            int hp = idx & 7;               // k-chunk 0..7
            int r  = idx >> 3;              // row 0..127
            int kt = hp >> 1, h = hp & 1;
            int cc = h * 16 + (r & 15);
            int cs = cc ^ ((4 * kt + 2 * h) & 7);
            uint32_t dst = stg + region * 16384 + kt * 4096 + (r >> 4) * 512 + cs * 16;
            const __half* sp;
            bool valid = true;
            if (region == 0) {
                sp = Ah + (size_t)(bm + r) * K + k0 + hp * 8;
            } else {
                int row = bn + r;
                valid = row < N;
                if (!valid) row = N - 1;
                sp = Bh + (size_t)row * K + k0 + hp * 8;
            }
            cp_async16(dst, sp, valid);
        }
    };

    auto compute = [&](int s) {
        uint32_t stg = base + (uint32_t)s * STG1_BYTES;
        #pragma unroll
        for (int kt = 0; kt < 4; kt++) {
            uint32_t sw = lsw[kt & 1];
            uint32_t bfr[4][4];
            #pragma unroll
            for (int np = 0; np < 4; np++) {
                uint32_t baddr = stg + 16384 + kt * 4096 + (wnt + np) * 512 + sw;
                ldsm_x4(bfr[np], baddr);
            }
            #pragma unroll
            for (int mt = 0; mt < 4; mt++) {
                uint32_t aaddr = stg + kt * 4096 + (wmt + mt) * 512 + sw;
                uint32_t ah[4];
                ldsm_x4(ah, aaddr);
                #pragma unroll
                for (int nt = 0; nt < 8; nt++) {
                    int np = nt >> 1, wq = nt & 1;
                    mma_f16(acc[mt][nt], ah, bfr[np][wq], bfr[np][wq + 2]);
                }
            }
        }
    };

    issue(0, 0); CP_COMMIT;
    issue(1, BK); CP_COMMIT;
    for (int b = 0; b < NB; b++) {
        if (b + 1 < NB) cp_wait<1>(); else cp_wait<0>();
        __syncthreads();
        compute(b % 3);
        if (b + 2 < NB) { issue((b + 2) % 3, (b + 2) * BK); CP_COMMIT; }
    }

    const int l4 = lane >> 2, l2 = (lane & 3) * 2;
    #pragma unroll
    for (int mt = 0; mt < 4; mt++) {
        int row = bm + wm + mt * 16 + l4;
        #pragma unroll
        for (int nt = 0; nt < 8; nt++) {
            int col = bn + wn + nt * 8 + l2;
            if (col < N) {
                float b0 = bias[col], b1 = bias[col + 1];
                float2 v0 = make_float2(acc[mt][nt][0] * oscale + b0,
                                        acc[mt][nt][1] * oscale + b1);
                float2 v1 = make_float2(acc[mt][nt][2] * oscale + b0,
                                        acc[mt][nt][3] * oscale + b1);
                *(float2*)&C[(size_t)row * N + col] = v0;
                *(float2*)&C[(size_t)(row + 8) * N + col] = v1;
            }
        }
    }
}

// ---------------- conversion kernels ----------------
__global__ void convert_hi(const float* __restrict__ src,
                           __half* __restrict__ hi, int n4)
{
    int i = blockIdx.x * blockDim.x + threadIdx.x;
    if (i >= n4) return;
    float4 v = *(const float4*)&src[(size_t)i * 4];
    __half h[4];
    h[0] = __float2half_rn(v.x);
    h[1] = __float2half_rn(v.y);
    h[2] = __float2half_rn(v.z);
    h[3] = __float2half_rn(v.w);
    *(uint2*)&hi[(size_t)i * 4] = *(uint2*)h;
}

// transpose + scale, hi only
__device__ __forceinline__ void cts_hi_body(
    const float* __restrict__ W, __half* __restrict__ hi,
    int K, int N, int out_off, int bx, int by, float tile[32][33])
{
    int tx = threadIdx.x, ty = threadIdx.y;
    int n0 = bx * 32, k0 = by * 32;
    #pragma unroll
    for (int j = 0; j < 4; j++)
        tile[ty + j * 8][tx] = W[(size_t)(k0 + ty + j * 8) * N + n0 + tx];
    __syncthreads();
    #pragma unroll
    for (int j = 0; j < 4; j++) {
        int n = n0 + ty + j * 8;
        float v = tile[tx][ty + j * 8] * WSCALE;
        hi[(size_t)(out_off + n) * K + k0 + tx] = __float2half_rn(v);
    }
}

__global__ __launch_bounds__(256) void cts_qkv_hi(
    const float* __restrict__ Wq, const float* __restrict__ Wk,
    const float* __restrict__ Wv, __half* __restrict__ hi)
{
    __shared__ float tile[32][33];
    int bx = blockIdx.x;
    const float* W; int N, off;
    if (bx < QSZ / 32) { W = Wq; N = QSZ; off = 0; }
    else if (bx < (QSZ + KVSZ) / 32) { W = Wk; N = KVSZ; off = QSZ; bx -= QSZ / 32; }
    else { W = Wv; N = KVSZ; off = QSZ + KVSZ; bx -= (QSZ + KVSZ) / 32; }
    cts_hi_body(W, hi, HID, N, off, bx, blockIdx.y, tile);
}

__global__ __launch_bounds__(256) void cts_wo_hi(
    const float* __restrict__ Wo, __half* __restrict__ hi)
{
    __shared__ float tile[32][33];
    cts_hi_body(Wo, hi, QSZ, HID, 0, blockIdx.x, blockIdx.y, tile);
}

__global__ void concat_bias(const float* __restrict__ a, const float* __restrict__ b,
                            const float* __restrict__ c, float* __restrict__ out)
{
    int i = blockIdx.x * blockDim.x + threadIdx.x;
    if (i >= QKVSZ) return;
    float v;
    if (i < QSZ) v = a[i];
    else if (i < QSZ + KVSZ) v = b[i - QSZ];
    else v = c[i - QSZ - KVSZ];
    out[i] = v;
}

// ---------------- NeoX RoPE over combined qkv (q heads + k heads) ----------------
__global__ void rope_kernel(float* __restrict__ qkv, const int* __restrict__ pos)
{
    int idx = blockIdx.x * blockDim.x + threadIdx.x;
    const int half = DD / 2;
    const int HR = HQ + HKV;  // 72 rope heads
    int total = TT * HR * half;
    if (idx >= total) return;
    int j = idx & 31;
    int h = (idx >> 5) % HR;
    int t = idx / (half * HR);

    float inv = powf(THETA, -(float)j / 32.0f);
    float ang = (float)pos[t] * inv;
    float c, s;
    sincosf(ang, &s, &c);

    int colb = (h < HQ) ? h * DD : QSZ + (h - HQ) * DD;
    float* base = qkv + (size_t)t * QKVSZ + colb;
    float x1 = base[j];
    float x2 = base[j + half];
    base[j]        = x1 * c - x2 * s;
    base[j + half] = x1 * s + x2 * c;
}

// ---------------- token-tiled sliding-window GQA attention ----------------
#define TQ 16
#define UROWS (WW + TQ)   // 144
#define KVP 68
#define PPAD 132
#define A_KS 0
#define A_VS (UROWS*KVP)
#define A_QS (2*UROWS*KVP)
#define A_PS (2*UROWS*KVP + TQ*GG*DD)
#define A_FLOATS (A_PS + TQ*GG*PPAD)
#define ATTN_SMEM (A_FLOATS*4)

__global__ __launch_bounds__(512) void attn_tiled(__half* __restrict__ out_hi)
{
    extern __shared__ float sm[];
    float* Ks = sm + A_KS;
    float* Vs = sm + A_VS;
    float* Qs = sm + A_QS;
    float* Ps = sm + A_PS;

    const int kh   = blockIdx.x;
    const int tile = blockIdx.y;
    const int b    = tile >> 6;
    const int i0   = (tile & 63) << 4;
    const int tid  = threadIdx.x;
    const int warp = tid >> 5;
    const int lane = tid & 31;

    for (int idx = tid; idx < UROWS * 16; idx += 512) {
        int u = idx >> 4, d4 = (idx & 15) * 4;
        int p = i0 - WW + u;
        float4 kv = make_float4(0.f, 0.f, 0.f, 0.f);
        float4 vv = make_float4(0.f, 0.f, 0.f, 0.f);
        if (p >= 0) {
            size_t off = (size_t)(b * SS + p) * QKVSZ + QSZ + kh * DD + d4;
            kv = *(const float4*)&g_qkv[off];
            vv = *(const float4*)&g_qkv[off + KVSZ];
        }
        *(float4*)&Ks[u * KVP + d4] = kv;
        *(float4*)&Vs[u * KVP + d4] = vv;
    }
    for (int idx = tid; idx < TQ * GG * 16; idx += 512) {
        int lt = idx >> 7, g = (idx >> 4) & 7, d4 = (idx & 15) * 4;
        size_t off = (size_t)(b * SS + i0 + lt) * QKVSZ + (kh * GG + g) * DD + d4;
        *(float4*)&Qs[(lt * GG + g) * DD + d4] = *(const float4*)&g_qkv[off];
    }
    __syncthreads();

    const int lt = warp;
    const int i  = i0 + lt;
    float* prow0 = &Ps[lt * GG * PPAD];

    {
        float acc[GG][4];
        #pragma unroll
        for (int g = 0; g < GG; g++)
            #pragma unroll
            for (int j = 0; j < 4; j++) acc[g][j] = 0.f;

        const float* kbase = &Ks[(lt + lane) * KVP];
        #pragma unroll
        for (int d4 = 0; d4 < DD; d4 += 4) {
            float4 k4[4];
            #pragma unroll
            for (int j = 0; j < 4; j++)
                k4[j] = *(const float4*)&kbase[j * 32 * KVP + d4];
            #pragma unroll
            for (int g = 0; g < GG; g++) {
                float4 q4 = *(const float4*)&Qs[(lt * GG + g) * DD + d4];
                #pragma unroll
                for (int j = 0; j < 4; j++) {
                    acc[g][j] += q4.x * k4[j].x + q4.y * k4[j].y
                               + q4.z * k4[j].z + q4.w * k4[j].w;
                }
            }
        }
        #pragma unroll
        for (int g = 0; g < GG; g++)
            #pragma unroll
            for (int j = 0; j < 4; j++) {
                int w = lane + j * 32;
                int p = i - WW + w;
                prow0[g * PPAD + w] = (p >= 0) ? acc[g][j] * SCALE : -1e30f;
            }
        if (lane < GG) {
            int g = lane;
            const float* kp = &Ks[(lt + WW) * KVP];
            const float* qp = &Qs[(lt * GG + g) * DD];
            float s = 0.f;
            #pragma unroll
            for (int d = 0; d < DD; d++) s += qp[d] * kp[d];
            prow0[g * PPAD + WW] = s * SCALE;
        }
    }
    __syncwarp();

    #pragma unroll
    for (int g = 0; g < GG; g++) {
        float* row = &prow0[g * PPAD];
        float m = -1e30f;
        for (int w = lane; w < 129; w += 32) m = fmaxf(m, row[w]);
        #pragma unroll
        for (int o = 16; o; o >>= 1) m = fmaxf(m, __shfl_xor_sync(0xffffffffu, m, o));
        float sum = 0.f;
        for (int w = lane; w < 129; w += 32) {
            float e = __expf(row[w] - m);
            row[w] = e;
            sum += e;
        }
        #pragma unroll
        for (int o = 16; o; o >>= 1) sum += __shfl_xor_sync(0xffffffffu, sum, o);
        float inv = 1.f / sum;
        for (int w = lane; w < 129; w += 32) row[w] *= inv;
    }
    __syncwarp();

    {
        const int d0 = lane * 2;
        float acc0[GG], acc1[GG];
        #pragma unroll
        for (int g = 0; g < GG; g++) { acc0[g] = 0.f; acc1[g] = 0.f; }

        for (int wb = 0; wb < WW; wb += 4) {
            float2 v2[4];
            #pragma unroll
            for (int j = 0; j < 4; j++)
                v2[j] = *(const float2*)&Vs[(lt + wb + j) * KVP + d0];
            #pragma unroll
            for (int g = 0; g < GG; g++) {
                float4 p4 = *(const float4*)&prow0[g * PPAD + wb];
                acc0[g] += p4.x * v2[0].x + p4.y * v2[1].x + p4.z * v2[2].x + p4.w * v2[3].x;
                acc1[g] += p4.x * v2[0].y + p4.y * v2[1].y + p4.z * v2[2].y + p4.w * v2[3].y;
            }
        }
        {
            float2 v2 = *(const float2*)&Vs[(lt + WW) * KVP + d0];
            #pragma unroll
            for (int g = 0; g < GG; g++) {
                float p = prow0[g * PPAD + WW];
                acc0[g] += p * v2.x;
                acc1[g] += p * v2.y;
            }
        }
        int t = b * SS + i;
        #pragma unroll
        for (int g = 0; g < GG; g++) {
            __half2 h2 = __floats2half2_rn(acc0[g], acc1[g]);
            *(__half2*)&out_hi[((size_t)t * HQ + kh * GG + g) * DD + d0] = h2;
        }
    }
}

// ---------------- launch ----------------
extern "C" void kernel_launch(void* const* d_in, const int* in_sizes, int n_in,
                              void* d_out, int out_size)
{
    const float* hs = (const float*)d_in[0];
    const int*  pos = (const int*)  d_in[1];
    const float* Wq = (const float*)d_in[2];
    const float* bq = (const float*)d_in[3];
    const float* Wk = (const float*)d_in[4];
    const float* bk = (const float*)d_in[5];
    const float* Wv = (const float*)d_in[6];
    const float* bv = (const float*)d_in[7];
    const float* Wo = (const float*)d_in[8];
    const float* bo = (const float*)d_in[9];
    float* out = (float*)d_out;

    __half *hs_hi, *wqkv_hi, *wo_hi, *att_hi;
    float *bqkv, *qkv;
    cudaGetSymbolAddress((void**)&hs_hi,   g_hs_hi);
    cudaGetSymbolAddress((void**)&wqkv_hi, g_Wqkv_hi);
    cudaGetSymbolAddress((void**)&bqkv,    g_bqkv);
    cudaGetSymbolAddress((void**)&qkv,     g_qkv);
    cudaGetSymbolAddress((void**)&wo_hi,   g_Wo_hi);
    cudaGetSymbolAddress((void**)&att_hi,  g_att_hi);

    cudaFuncSetAttribute(gemm_f16single, cudaFuncAttributeMaxDynamicSharedMemorySize, GEMM1_SMEM);
    cudaFuncSetAttribute(attn_tiled, cudaFuncAttributeMaxDynamicSharedMemorySize, ATTN_SMEM);

    // (0) combined bias
    concat_bias<<<(QKVSZ + 255) / 256, 256>>>(bq, bk, bv, bqkv);
    // (1) hidden_states -> fp16 hi
    {
        int n4 = TT * HID / 4;
        convert_hi<<<(n4 + 255) / 256, 256>>>(hs, hs_hi, n4);
    }
    // (2) fused QKV weight transpose (hi only)
    {
        dim3 blk(32, 8);
        cts_qkv_hi<<<dim3(QKVSZ / 32, HID / 32), blk>>>(Wq, Wk, Wv, wqkv_hi);
    }
    // (3) fused QKV projection  <-- profiled slot
    gemm_f16single<<<dim3(QKVSZ / 128, TT / 128), 128, GEMM1_SMEM>>>(
        hs_hi, wqkv_hi, bqkv, qkv, TT, QKVSZ, HID, OSCALE);
    // (4) Wo transpose (hi only)
    {
        dim3 blk(32, 8);
        cts_wo_hi<<<dim3(HID / 32, QSZ / 32), blk>>>(Wo, wo_hi);
    }
    // (5) RoPE on q + k heads
    {
        int tot = TT * (HQ + HKV) * (DD / 2);
        rope_kernel<<<(tot + 255) / 256, 256>>>(qkv, pos);
    }
    // (6) token-tiled attention
    {
        dim3 ga(HKV, TT / TQ);
        attn_tiled<<<ga, 512, ATTN_SMEM>>>(att_hi);
    }
    // (7) output projection
    gemm_f16single<<<dim3((HID + 127) / 128, TT / 128), 128, GEMM1_SMEM>>>(
        att_hi, wo_hi, bo, out, TT, HID, QSZ, OSCALE);
}

// round 14
// speedup vs baseline: 1.6485x; 1.6485x over previous
#include <cuda_runtime.h>
#include <cuda_fp16.h>
#include <cstdint>

// ---------------- problem constants ----------------
#define BB 2
#define SS 1024
#define TT (BB*SS)      // 2048 tokens
#define HID 2880
#define HQ 64
#define HKV 8
#define DD 64
#define GG (HQ/HKV)     // 8
#define WW 128
#define QSZ (HQ*DD)     // 4096
#define KVSZ (HKV*DD)   // 512
#define QKVSZ (QSZ + 2*KVSZ)  // 5120
#define SCALE 0.125f
#define THETA 150000.0f
#define WSCALE 64.0f
#define OSCALE (1.0f/64.0f)

// ---------------- scratch (no allocation allowed) ----------------
__device__ __half g_hs_hi[TT*HID];
__device__ __half g_Wqkv_hi[QKVSZ*HID];   // [n][k] K-major, combined q|k|v order
__device__ float  g_bqkv[QKVSZ];
__device__ float  g_qkv[TT*QKVSZ];        // q | k | v per token (pre-rope)
__device__ __half g_Wo_hi[HID*QSZ];       // [n=HID][k=QSZ]
__device__ __half g_att_hi[TT*QSZ];
__device__ float  g_cos[SS*32];
__device__ float  g_sin[SS*32];

// ---------------- low-level helpers ----------------
__device__ __forceinline__ uint32_t smem_u32(const void* p) {
    uint32_t a;
    asm("{ .reg .u64 t; cvta.to.shared.u64 t, %1; cvt.u32.u64 %0, t; }" : "=r"(a) : "l"(p));
    return a;
}

__device__ __forceinline__ void cp_async16(uint32_t dst, const void* src, bool valid) {
    int sz = valid ? 16 : 0;
    asm volatile("cp.async.cg.shared.global [%0], [%1], 16, %2;"
                 :: "r"(dst), "l"(src), "r"(sz));
}
#define CP_COMMIT asm volatile("cp.async.commit_group;")
template<int NN> __device__ __forceinline__ void cp_wait() {
    asm volatile("cp.async.wait_group %0;" :: "n"(NN));
}

__device__ __forceinline__ void ldsm_x4(uint32_t r[4], uint32_t addr) {
    asm volatile("ldmatrix.sync.aligned.m8n8.x4.shared.b16 {%0,%1,%2,%3}, [%4];"
        : "=r"(r[0]), "=r"(r[1]), "=r"(r[2]), "=r"(r[3]) : "r"(addr));
}

__device__ __forceinline__ void mma_f16(float c[4], const uint32_t a[4],
                                        uint32_t b0, uint32_t b1) {
    asm volatile(
        "mma.sync.aligned.m16n8k16.row.col.f32.f16.f16.f32 "
        "{%0,%1,%2,%3}, {%4,%5,%6,%7}, {%8,%9}, {%0,%1,%2,%3};"
        : "+f"(c[0]), "+f"(c[1]), "+f"(c[2]), "+f"(c[3])
        : "r"(a[0]), "r"(a[1]), "r"(a[2]), "r"(a[3]), "r"(b0), "r"(b1));
}

// ---------------- fp16 single-pass GEMM, BK=64 (R12 config, best) ----------------
#define BK 64
#define STG1_BYTES 32768
#define GEMM1_SMEM (3*STG1_BYTES + 128)

__global__ __launch_bounds__(256, 2) void gemm_f16single(
    const __half* __restrict__ Ah, const __half* __restrict__ Bh,
    const float* __restrict__ bias, float* __restrict__ C,
    int M, int N, int K, float oscale)
{
    extern __shared__ char raw[];
    const uint32_t base = (smem_u32(raw) + 127u) & ~127u;

    const int tid  = threadIdx.x;
    const int warp = tid >> 5, lane = tid & 31;
    const int bm = blockIdx.y * 128;
    const int bn = blockIdx.x * 128;
    const int wm = (warp >> 2) * 64;
    const int wn = (warp & 3) * 32;
    const int wmt = wm >> 4;
    const int wnt = wn >> 4;

    float acc[4][4][4];
    #pragma unroll
    for (int i = 0; i < 4; i++)
        #pragma unroll
        for (int j = 0; j < 4; j++)
            #pragma unroll
            for (int c = 0; c < 4; c++) acc[i][j][c] = 0.f;

    uint32_t lsw[2];
    {
        int h = lane >> 4;
        lsw[0] = (uint32_t)((lane ^ ((2 * h) & 7)) * 16);
        lsw[1] = (uint32_t)((lane ^ ((4 + 2 * h) & 7)) * 16);
    }

    const int NB = K / BK;

    auto issue = [&](int s, int k0) {
        uint32_t stg = base + (uint32_t)s * STG1_BYTES;
        #pragma unroll
        for (int i = 0; i < 8; i++) {
            int region = i >> 2;            // 0 A, 1 B
            int idx = tid + (i & 3) * 256;  // 0..1023
            int hp = idx & 7;               // k-chunk 0..7
            int r  = idx >> 3;              // row 0..127
            int kt = hp >> 1, h = hp & 1;
            int cc = h * 16 + (r & 15);
            int cs = cc ^ ((4 * kt + 2 * h) & 7);
            uint32_t dst = stg + region * 16384 + kt * 4096 + (r >> 4) * 512 + cs * 16;
            const __half* sp;
            bool valid = true;
            if (region == 0) {
                sp = Ah + (size_t)(bm + r) * K + k0 + hp * 8;
            } else {
                int row = bn + r;
                valid = row < N;
                if (!valid) row = N - 1;
                sp = Bh + (size_t)row * K + k0 + hp * 8;
            }
            cp_async16(dst, sp, valid);
        }
    };

    auto compute = [&](int s) {
        uint32_t stg = base + (uint32_t)s * STG1_BYTES;
        #pragma unroll
        for (int kt = 0; kt < 4; kt++) {
            uint32_t sw = lsw[kt & 1];
            uint32_t bfr[2][4];
            #pragma unroll
            for (int np = 0; np < 2; np++) {
                uint32_t baddr = stg + 16384 + kt * 4096 + (wnt + np) * 512 + sw;
                ldsm_x4(bfr[np], baddr);
            }
            #pragma unroll
            for (int mt = 0; mt < 4; mt++) {
                uint32_t aaddr = stg + kt * 4096 + (wmt + mt) * 512 + sw;
                uint32_t ah[4];
                ldsm_x4(ah, aaddr);
                #pragma unroll
                for (int nt = 0; nt < 4; nt++) {
                    int np = nt >> 1, wq = nt & 1;
                    mma_f16(acc[mt][nt], ah, bfr[np][wq], bfr[np][wq + 2]);
                }
            }
        }
    };

    issue(0, 0); CP_COMMIT;
    issue(1, BK); CP_COMMIT;
    for (int b = 0; b < NB; b++) {
        if (b + 1 < NB) cp_wait<1>(); else cp_wait<0>();
        __syncthreads();
        compute(b % 3);
        if (b + 2 < NB) { issue((b + 2) % 3, (b + 2) * BK); CP_COMMIT; }
    }

    const int l4 = lane >> 2, l2 = (lane & 3) * 2;
    #pragma unroll
    for (int mt = 0; mt < 4; mt++) {
        int row = bm + wm + mt * 16 + l4;
        #pragma unroll
        for (int nt = 0; nt < 4; nt++) {
            int col = bn + wn + nt * 8 + l2;
            if (col < N) {
                float b0 = bias[col], b1 = bias[col + 1];
                float2 v0 = make_float2(acc[mt][nt][0] * oscale + b0,
                                        acc[mt][nt][1] * oscale + b1);
                float2 v1 = make_float2(acc[mt][nt][2] * oscale + b0,
                                        acc[mt][nt][3] * oscale + b1);
                *(float2*)&C[(size_t)row * N + col] = v0;
                *(float2*)&C[(size_t)(row + 8) * N + col] = v1;
            }
        }
    }
}

// ---------------- conversion kernels ----------------
__global__ void convert_hi(const float* __restrict__ src,
                           __half* __restrict__ hi, int n4)
{
    int i = blockIdx.x * blockDim.x + threadIdx.x;
    if (i >= n4) return;
    float4 v = *(const float4*)&src[(size_t)i * 4];
    __half h[4];
    h[0] = __float2half_rn(v.x);
    h[1] = __float2half_rn(v.y);
    h[2] = __float2half_rn(v.z);
    h[3] = __float2half_rn(v.w);
    *(uint2*)&hi[(size_t)i * 4] = *(uint2*)h;
}

__device__ __forceinline__ void cts_hi_body(
    const float* __restrict__ W, __half* __restrict__ hi,
    int K, int N, int out_off, int bx, int by, float tile[32][33])
{
    int tx = threadIdx.x, ty = threadIdx.y;
    int n0 = bx * 32, k0 = by * 32;
    #pragma unroll
    for (int j = 0; j < 4; j++)
        tile[ty + j * 8][tx] = W[(size_t)(k0 + ty + j * 8) * N + n0 + tx];
    __syncthreads();
    #pragma unroll
    for (int j = 0; j < 4; j++) {
        int n = n0 + ty + j * 8;
        float v = tile[tx][ty + j * 8] * WSCALE;
        hi[(size_t)(out_off + n) * K + k0 + tx] = __float2half_rn(v);
    }
}

__global__ __launch_bounds__(256) void cts_qkv_hi(
    const float* __restrict__ Wq, const float* __restrict__ Wk,
    const float* __restrict__ Wv, __half* __restrict__ hi)
{
    __shared__ float tile[32][33];
    int bx = blockIdx.x;
    const float* W; int N, off;
    if (bx < QSZ / 32) { W = Wq; N = QSZ; off = 0; }
    else if (bx < (QSZ + KVSZ) / 32) { W = Wk; N = KVSZ; off = QSZ; bx -= QSZ / 32; }
    else { W = Wv; N = KVSZ; off = QSZ + KVSZ; bx -= (QSZ + KVSZ) / 32; }
    cts_hi_body(W, hi, HID, N, off, bx, blockIdx.y, tile);
}

__global__ __launch_bounds__(256) void cts_wo_hi(
    const float* __restrict__ Wo, __half* __restrict__ hi)
{
    __shared__ float tile[32][33];
    cts_hi_body(Wo, hi, QSZ, HID, 0, blockIdx.x, blockIdx.y, tile);
}

__global__ void concat_bias(const float* __restrict__ a, const float* __restrict__ b,
                            const float* __restrict__ c, float* __restrict__ out)
{
    int i = blockIdx.x * blockDim.x + threadIdx.x;
    if (i >= QKVSZ) return;
    float v;
    if (i < QSZ) v = a[i];
    else if (i < QSZ + KVSZ) v = b[i - QSZ];
    else v = c[i - QSZ - KVSZ];
    out[i] = v;
}

// ---------------- RoPE cos/sin table (position value 0..SS-1, j 0..31) ----------------
__global__ void rope_table()
{
    int idx = blockIdx.x * blockDim.x + threadIdx.x;
    if (idx >= SS * 32) return;
    int p = idx >> 5, j = idx & 31;
    float inv = powf(THETA, -(float)j / 32.0f);
    float ang = (float)p * inv;
    float c, s;
    sincosf(ang, &s, &c);
    g_cos[idx] = c;
    g_sin[idx] = s;
}

// ---------------- token-tiled attention with fused RoPE staging ----------------
#define TQ 16
#define UROWS (WW + TQ)   // 144
#define KVP 68
#define PPAD 132
#define A_KS 0
#define A_VS (UROWS*KVP)
#define A_QS (2*UROWS*KVP)
#define A_PS (2*UROWS*KVP + TQ*GG*DD)
#define A_FLOATS (A_PS + TQ*GG*PPAD)
#define ATTN_SMEM (A_FLOATS*4)

__global__ __launch_bounds__(512) void attn_tiled(
    const int* __restrict__ pos, __half* __restrict__ out_hi)
{
    extern __shared__ float sm[];
    float* Ks = sm + A_KS;
    float* Vs = sm + A_VS;
    float* Qs = sm + A_QS;
    float* Ps = sm + A_PS;

    const int khd  = blockIdx.x;
    const int tile = blockIdx.y;
    const int b    = tile >> 6;
    const int i0   = (tile & 63) << 4;
    const int tid  = threadIdx.x;
    const int warp = tid >> 5;
    const int lane = tid & 31;

    // ---- stage K (rope-rotated) + V (plain): chunks of 4 over lower half ----
    for (int idx = tid; idx < UROWS * 8; idx += 512) {
        int u = idx >> 3, c4 = (idx & 7) * 4;   // c4 in {0,4,...,28}
        int p = i0 - WW + u;
        float4 kl = make_float4(0.f,0.f,0.f,0.f), kh = kl;
        float4 vl = kl, vh = kl;
        if (p >= 0) {
            int t = b * SS + p;
            size_t off = (size_t)t * QKVSZ + QSZ + khd * DD;
            float4 a = *(const float4*)&g_qkv[off + c4];
            float4 bq_ = *(const float4*)&g_qkv[off + c4 + 32];
            vl = *(const float4*)&g_qkv[off + KVSZ + c4];
            vh = *(const float4*)&g_qkv[off + KVSZ + c4 + 32];
            int pv = pos[t];
            float4 c = *(const float4*)&g_cos[pv * 32 + c4];
            float4 s = *(const float4*)&g_sin[pv * 32 + c4];
            kl.x = a.x * c.x - bq_.x * s.x;  kh.x = a.x * s.x + bq_.x * c.x;
            kl.y = a.y * c.y - bq_.y * s.y;  kh.y = a.y * s.y + bq_.y * c.y;
            kl.z = a.z * c.z - bq_.z * s.z;  kh.z = a.z * s.z + bq_.z * c.z;
            kl.w = a.w * c.w - bq_.w * s.w;  kh.w = a.w * s.w + bq_.w * c.w;
        }
        *(float4*)&Ks[u * KVP + c4]      = kl;
        *(float4*)&Ks[u * KVP + c4 + 32] = kh;
        *(float4*)&Vs[u * KVP + c4]      = vl;
        *(float4*)&Vs[u * KVP + c4 + 32] = vh;
    }
    // ---- stage Q (rope-rotated): [lt][g][64] ----
    for (int idx = tid; idx < TQ * GG * 8; idx += 512) {
        int lt = idx >> 6, g = (idx >> 3) & 7, c4 = (idx & 7) * 4;
        int t = b * SS + i0 + lt;
        size_t off = (size_t)t * QKVSZ + (khd * GG + g) * DD;
        float4 a = *(const float4*)&g_qkv[off + c4];
        float4 bq_ = *(const float4*)&g_qkv[off + c4 + 32];
        int pv = pos[t];
        float4 c = *(const float4*)&g_cos[pv * 32 + c4];
        float4 s = *(const float4*)&g_sin[pv * 32 + c4];
        float4 ql, qh;
        ql.x = a.x * c.x - bq_.x * s.x;  qh.x = a.x * s.x + bq_.x * c.x;
        ql.y = a.y * c.y - bq_.y * s.y;  qh.y = a.y * s.y + bq_.y * c.y;
        ql.z = a.z * c.z - bq_.z * s.z;  qh.z = a.z * s.z + bq_.z * c.z;
        ql.w = a.w * c.w - bq_.w * s.w;  qh.w = a.w * s.w + bq_.w * c.w;
        *(float4*)&Qs[(lt * GG + g) * DD + c4]      = ql;
        *(float4*)&Qs[(lt * GG + g) * DD + c4 + 32] = qh;
    }
    __syncthreads();

    const int lt = warp;
    const int i  = i0 + lt;
    float* prow0 = &Ps[lt * GG * PPAD];

    {
        float acc[GG][4];
        #pragma unroll
        for (int g = 0; g < GG; g++)
            #pragma unroll
            for (int j = 0; j < 4; j++) acc[g][j] = 0.f;

        const float* kbase = &Ks[(lt + lane) * KVP];
        #pragma unroll
        for (int d4 = 0; d4 < DD; d4 += 4) {
            float4 k4[4];
            #pragma unroll
            for (int j = 0; j < 4; j++)
                k4[j] = *(const float4*)&kbase[j * 32 * KVP + d4];
            #pragma unroll
            for (int g = 0; g < GG; g++) {
                float4 q4 = *(const float4*)&Qs[(lt * GG + g) * DD + d4];
                #pragma unroll
                for (int j = 0; j < 4; j++) {
                    acc[g][j] += q4.x * k4[j].x + q4.y * k4[j].y
                               + q4.z * k4[j].z + q4.w * k4[j].w;
                }
            }
        }
        #pragma unroll
        for (int g = 0; g < GG; g++)
            #pragma unroll
            for (int j = 0; j < 4; j++) {
                int w = lane + j * 32;
                int p = i - WW + w;
                prow0[g * PPAD + w] = (p >= 0) ? acc[g][j] * SCALE : -1e30f;
            }
        if (lane < GG) {
            int g = lane;
            const float* kp = &Ks[(lt + WW) * KVP];
            const float* qp = &Qs[(lt * GG + g) * DD];
            float s = 0.f;
            #pragma unroll
            for (int d = 0; d < DD; d++) s += qp[d] * kp[d];
            prow0[g * PPAD + WW] = s * SCALE;
        }
    }
    __syncwarp();

    #pragma unroll
    for (int g = 0; g < GG; g++) {
        float* row = &prow0[g * PPAD];
        float m = -1e30f;
        for (int w = lane; w < 129; w += 32) m = fmaxf(m, row[w]);
        #pragma unroll
        for (int o = 16; o; o >>= 1) m = fmaxf(m, __shfl_xor_sync(0xffffffffu, m, o));
        float sum = 0.f;
        for (int w = lane; w < 129; w += 32) {
            float e = __expf(row[w] - m);
            row[w] = e;
            sum += e;
        }
        #pragma unroll
        for (int o = 16; o; o >>= 1) sum += __shfl_xor_sync(0xffffffffu, sum, o);
        float inv = 1.f / sum;
        for (int w = lane; w < 129; w += 32) row[w] *= inv;
    }
    __syncwarp();

    {
        const int d0 = lane * 2;
        float acc0[GG], acc1[GG];
        #pragma unroll
        for (int g = 0; g < GG; g++) { acc0[g] = 0.f; acc1[g] = 0.f; }

        for (int wb = 0; wb < WW; wb += 4) {
            float2 v2[4];
            #pragma unroll
            for (int j = 0; j < 4; j++)
                v2[j] = *(const float2*)&Vs[(lt + wb + j) * KVP + d0];
            #pragma unroll
            for (int g = 0; g < GG; g++) {
                float4 p4 = *(const float4*)&prow0[g * PPAD + wb];
                acc0[g] += p4.x * v2[0].x + p4.y * v2[1].x + p4.z * v2[2].x + p4.w * v2[3].x;
                acc1[g] += p4.x * v2[0].y + p4.y * v2[1].y + p4.z * v2[2].y + p4.w * v2[3].y;
            }
        }
        {
            float2 v2 = *(const float2*)&Vs[(lt + WW) * KVP + d0];
            #pragma unroll
            for (int g = 0; g < GG; g++) {
                float p = prow0[g * PPAD + WW];
                acc0[g] += p * v2.x;
                acc1[g] += p * v2.y;
            }
        }
        int t = b * SS + i;
        #pragma unroll
        for (int g = 0; g < GG; g++) {
            __half2 h2 = __floats2half2_rn(acc0[g], acc1[g]);
            *(__half2*)&out_hi[((size_t)t * HQ + khd * GG + g) * DD + d0] = h2;
        }
    }
}

// ---------------- launch ----------------
extern "C" void kernel_launch(void* const* d_in, const int* in_sizes, int n_in,
                              void* d_out, int out_size)
{
    const float* hs = (const float*)d_in[0];
    const int*  pos = (const int*)  d_in[1];
    const float* Wq = (const float*)d_in[2];
    const float* bq = (const float*)d_in[3];
    const float* Wk = (const float*)d_in[4];
    const float* bk = (const float*)d_in[5];
    const float* Wv = (const float*)d_in[6];
    const float* bv = (const float*)d_in[7];
    const float* Wo = (const float*)d_in[8];
    const float* bo = (const float*)d_in[9];
    float* out = (float*)d_out;

    __half *hs_hi, *wqkv_hi, *wo_hi, *att_hi;
    float *bqkv, *qkv;
    cudaGetSymbolAddress((void**)&hs_hi,   g_hs_hi);
    cudaGetSymbolAddress((void**)&wqkv_hi, g_Wqkv_hi);
    cudaGetSymbolAddress((void**)&bqkv,    g_bqkv);
    cudaGetSymbolAddress((void**)&qkv,     g_qkv);
    cudaGetSymbolAddress((void**)&wo_hi,   g_Wo_hi);
    cudaGetSymbolAddress((void**)&att_hi,  g_att_hi);

    cudaFuncSetAttribute(gemm_f16single, cudaFuncAttributeMaxDynamicSharedMemorySize, GEMM1_SMEM);
    cudaFuncSetAttribute(attn_tiled, cudaFuncAttributeMaxDynamicSharedMemorySize, ATTN_SMEM);

    // (0) combined bias
    concat_bias<<<(QKVSZ + 255) / 256, 256>>>(bq, bk, bv, bqkv);
    // (1) hidden_states -> fp16 hi
    {
        int n4 = TT * HID / 4;
        convert_hi<<<(n4 + 255) / 256, 256>>>(hs, hs_hi, n4);
    }
    // (2) fused QKV weight transpose (hi only)
    {
        dim3 blk(32, 8);
        cts_qkv_hi<<<dim3(QKVSZ / 32, HID / 32), blk>>>(Wq, Wk, Wv, wqkv_hi);
    }
    // (3) fused QKV projection (BK=64, R12 config)  <-- profiled slot
    gemm_f16single<<<dim3(QKVSZ / 128, TT / 128), 256, GEMM1_SMEM>>>(
        hs_hi, wqkv_hi, bqkv, qkv, TT, QKVSZ, HID, OSCALE);
    // (4) rope cos/sin table
    rope_table<<<(SS * 32 + 255) / 256, 256>>>();
    // (5) Wo transpose (hi only)
    {
        dim3 blk(32, 8);
        cts_wo_hi<<<dim3(HID / 32, QSZ / 32), blk>>>(Wo, wo_hi);
    }
    // (6) attention with fused RoPE staging
    {
        dim3 ga(HKV, TT / TQ);
        attn_tiled<<<ga, 512, ATTN_SMEM>>>(pos, att_hi);
    }
    // (7) output projection (BK=64)
    gemm_f16single<<<dim3((HID + 127) / 128, TT / 128), 256, GEMM1_SMEM>>>(
        att_hi, wo_hi, bo, out, TT, HID, QSZ, OSCALE);
}

// round 16
// speedup vs baseline: 1.6693x; 1.0126x over previous
#include <cuda_runtime.h>
#include <cuda_fp16.h>
#include <cstdint>

// ---------------- problem constants ----------------
#define BB 2
#define SS 1024
#define TT (BB*SS)      // 2048 tokens
#define HID 2880
#define HQ 64
#define HKV 8
#define DD 64
#define GG (HQ/HKV)     // 8
#define WW 128
#define QSZ (HQ*DD)     // 4096
#define KVSZ (HKV*DD)   // 512
#define QKVSZ (QSZ + 2*KVSZ)  // 5120
#define SCALE 0.125f
#define THETA 150000.0f
#define WSCALE 64.0f
#define OSCALE (1.0f/64.0f)

// ---------------- scratch (no allocation allowed) ----------------
__device__ __half g_hs_hi[TT*HID];
__device__ __half g_Wqkv_hi[QKVSZ*HID];   // [n][k] K-major, combined q|k|v order
__device__ float  g_bqkv[QKVSZ];
__device__ float  g_qkv[TT*QKVSZ];        // q | k | v per token (pre-rope)
__device__ __half g_Wo_hi[HID*QSZ];       // [n=HID][k=QSZ]
__device__ __half g_att_hi[TT*QSZ];
__device__ float  g_cos[SS*32];
__device__ float  g_sin[SS*32];

// ---------------- low-level helpers ----------------
__device__ __forceinline__ uint32_t smem_u32(const void* p) {
    uint32_t a;
    asm("{ .reg .u64 t; cvta.to.shared.u64 t, %1; cvt.u32.u64 %0, t; }" : "=r"(a) : "l"(p));
    return a;
}

__device__ __forceinline__ void cp_async16(uint32_t dst, const void* src, bool valid) {
    int sz = valid ? 16 : 0;
    asm volatile("cp.async.cg.shared.global [%0], [%1], 16, %2;"
                 :: "r"(dst), "l"(src), "r"(sz));
}
#define CP_COMMIT asm volatile("cp.async.commit_group;")
template<int NN> __device__ __forceinline__ void cp_wait() {
    asm volatile("cp.async.wait_group %0;" :: "n"(NN));
}

__device__ __forceinline__ void ldsm_x4(uint32_t r[4], uint32_t addr) {
    asm volatile("ldmatrix.sync.aligned.m8n8.x4.shared.b16 {%0,%1,%2,%3}, [%4];"
        : "=r"(r[0]), "=r"(r[1]), "=r"(r[2]), "=r"(r[3]) : "r"(addr));
}

__device__ __forceinline__ void mma_f16(float c[4], const uint32_t a[4],
                                        uint32_t b0, uint32_t b1) {
    asm volatile(
        "mma.sync.aligned.m16n8k16.row.col.f32.f16.f16.f32 "
        "{%0,%1,%2,%3}, {%4,%5,%6,%7}, {%8,%9}, {%0,%1,%2,%3};"
        : "+f"(c[0]), "+f"(c[1]), "+f"(c[2]), "+f"(c[3])
        : "r"(a[0]), "r"(a[1]), "r"(a[2]), "r"(a[3]), "r"(b0), "r"(b1));
}

// ---------------- fp16 single-pass GEMM, BK=64, 512 threads ----------------
// C[M,N] = (Ah[M,K] @ BTh[N,K]^T) * oscale + bias.
// CTA tile 128x128, BK=64, 512 threads / 16 warps, warp tile 32x32.
// 32 warps/SM at 2 CTAs; hot regs: acc 32 + frags 12 < 64-reg cap (no spill).
// Per stage (32KB): [Ah 16K | Bh 16K], 4 ktiles each. 3 stages.
#define BK 64
#define STG1_BYTES 32768
#define GEMM1_SMEM (3*STG1_BYTES + 128)

__global__ __launch_bounds__(512, 2) void gemm_f16single(
    const __half* __restrict__ Ah, const __half* __restrict__ Bh,
    const float* __restrict__ bias, float* __restrict__ C,
    int M, int N, int K, float oscale)
{
    extern __shared__ char raw[];
    const uint32_t base = (smem_u32(raw) + 127u) & ~127u;

    const int tid  = threadIdx.x;
    const int warp = tid >> 5, lane = tid & 31;
    const int bm = blockIdx.y * 128;
    const int bn = blockIdx.x * 128;
    const int wm = (warp >> 2) * 32;    // 0,32,64,96
    const int wn = (warp & 3) * 32;     // 0,32,64,96
    const int wmt = wm >> 4;            // 0,2,4,6
    const int wnt = wn >> 4;            // 0,2,4,6

    float acc[2][4][4];
    #pragma unroll
    for (int i = 0; i < 2; i++)
        #pragma unroll
        for (int j = 0; j < 4; j++)
            #pragma unroll
            for (int c = 0; c < 4; c++) acc[i][j][c] = 0.f;

    uint32_t lsw[2];
    {
        int h = lane >> 4;
        lsw[0] = (uint32_t)((lane ^ ((2 * h) & 7)) * 16);
        lsw[1] = (uint32_t)((lane ^ ((4 + 2 * h) & 7)) * 16);
    }

    const int NB = K / BK;

    auto issue = [&](int s, int k0) {
        uint32_t stg = base + (uint32_t)s * STG1_BYTES;
        #pragma unroll
        for (int i = 0; i < 4; i++) {
            int region = i >> 1;            // 0 A, 1 B
            int idx = tid + (i & 1) * 512;  // 0..1023
            int hp = idx & 7;               // k-chunk 0..7
            int r  = idx >> 3;              // row 0..127
            int kt = hp >> 1, h = hp & 1;
            int cc = h * 16 + (r & 15);
            int cs = cc ^ ((4 * kt + 2 * h) & 7);
            uint32_t dst = stg + region * 16384 + kt * 4096 + (r >> 4) * 512 + cs * 16;
            const __half* sp;
            bool valid = true;
            if (region == 0) {
                sp = Ah + (size_t)(bm + r) * K + k0 + hp * 8;
            } else {
                int row = bn + r;
                valid = row < N;
                if (!valid) row = N - 1;
                sp = Bh + (size_t)row * K + k0 + hp * 8;
            }
            cp_async16(dst, sp, valid);
        }
    };

    auto compute = [&](int s) {
        uint32_t stg = base + (uint32_t)s * STG1_BYTES;
        #pragma unroll
        for (int kt = 0; kt < 4; kt++) {
            uint32_t sw = lsw[kt & 1];
            uint32_t bfr[2][4];
            #pragma unroll
            for (int np = 0; np < 2; np++) {
                uint32_t baddr = stg + 16384 + kt * 4096 + (wnt + np) * 512 + sw;
                ldsm_x4(bfr[np], baddr);
            }
            #pragma unroll
            for (int mt = 0; mt < 2; mt++) {
                uint32_t aaddr = stg + kt * 4096 + (wmt + mt) * 512 + sw;
                uint32_t ah[4];
                ldsm_x4(ah, aaddr);
                #pragma unroll
                for (int nt = 0; nt < 4; nt++) {
                    int np = nt >> 1, wq = nt & 1;
                    mma_f16(acc[mt][nt], ah, bfr[np][wq], bfr[np][wq + 2]);
                }
            }
        }
    };

    issue(0, 0); CP_COMMIT;
    issue(1, BK); CP_COMMIT;
    for (int b = 0; b < NB; b++) {
        if (b + 1 < NB) cp_wait<1>(); else cp_wait<0>();
        __syncthreads();
        compute(b % 3);
        if (b + 2 < NB) { issue((b + 2) % 3, (b + 2) * BK); CP_COMMIT; }
    }

    const int l4 = lane >> 2, l2 = (lane & 3) * 2;
    #pragma unroll
    for (int mt = 0; mt < 2; mt++) {
        int row = bm + wm + mt * 16 + l4;
        #pragma unroll
        for (int nt = 0; nt < 4; nt++) {
            int col = bn + wn + nt * 8 + l2;
            if (col < N) {
                float b0 = bias[col], b1 = bias[col + 1];
                float2 v0 = make_float2(acc[mt][nt][0] * oscale + b0,
                                        acc[mt][nt][1] * oscale + b1);
                float2 v1 = make_float2(acc[mt][nt][2] * oscale + b0,
                                        acc[mt][nt][3] * oscale + b1);
                *(float2*)&C[(size_t)row * N + col] = v0;
                *(float2*)&C[(size_t)(row + 8) * N + col] = v1;
            }
        }
    }
}

// ---------------- conversion kernels ----------------
__global__ void convert_hi(const float* __restrict__ src,
                           __half* __restrict__ hi, int n4)
{
    int i = blockIdx.x * blockDim.x + threadIdx.x;
    if (i >= n4) return;
    float4 v = *(const float4*)&src[(size_t)i * 4];
    __half h[4];
    h[0] = __float2half_rn(v.x);
    h[1] = __float2half_rn(v.y);
    h[2] = __float2half_rn(v.z);
    h[3] = __float2half_rn(v.w);
    *(uint2*)&hi[(size_t)i * 4] = *(uint2*)h;
}

__device__ __forceinline__ void cts_hi_body(
    const float* __restrict__ W, __half* __restrict__ hi,
    int K, int N, int out_off, int bx, int by, float tile[32][33])
{
    int tx = threadIdx.x, ty = threadIdx.y;
    int n0 = bx * 32, k0 = by * 32;
    #pragma unroll
    for (int j = 0; j < 4; j++)
        tile[ty + j * 8][tx] = W[(size_t)(k0 + ty + j * 8) * N + n0 + tx];
    __syncthreads();
    #pragma unroll
    for (int j = 0; j < 4; j++) {
        int n = n0 + ty + j * 8;
        float v = tile[tx][ty + j * 8] * WSCALE;
        hi[(size_t)(out_off + n) * K + k0 + tx] = __float2half_rn(v);
    }
}

__global__ __launch_bounds__(256) void cts_qkv_hi(
    const float* __restrict__ Wq, const float* __restrict__ Wk,
    const float* __restrict__ Wv, __half* __restrict__ hi)
{
    __shared__ float tile[32][33];
    int bx = blockIdx.x;
    const float* W; int N, off;
    if (bx < QSZ / 32) { W = Wq; N = QSZ; off = 0; }
    else if (bx < (QSZ + KVSZ) / 32) { W = Wk; N = KVSZ; off = QSZ; bx -= QSZ / 32; }
    else { W = Wv; N = KVSZ; off = QSZ + KVSZ; bx -= (QSZ + KVSZ) / 32; }
    cts_hi_body(W, hi, HID, N, off, bx, blockIdx.y, tile);
}

__global__ __launch_bounds__(256) void cts_wo_hi(
    const float* __restrict__ Wo, __half* __restrict__ hi)
{
    __shared__ float tile[32][33];
    cts_hi_body(Wo, hi, QSZ, HID, 0, blockIdx.x, blockIdx.y, tile);
}

__global__ void concat_bias(const float* __restrict__ a, const float* __restrict__ b,
                            const float* __restrict__ c, float* __restrict__ out)
{
    int i = blockIdx.x * blockDim.x + threadIdx.x;
    if (i >= QKVSZ) return;
    float v;
    if (i < QSZ) v = a[i];
    else if (i < QSZ + KVSZ) v = b[i - QSZ];
    else v = c[i - QSZ - KVSZ];
    out[i] = v;
}

// ---------------- RoPE cos/sin table ----------------
__global__ void rope_table()
{
    int idx = blockIdx.x * blockDim.x + threadIdx.x;
    if (idx >= SS * 32) return;
    int p = idx >> 5, j = idx & 31;
    float inv = powf(THETA, -(float)j / 32.0f);
    float ang = (float)p * inv;
    float c, s;
    sincosf(ang, &s, &c);
    g_cos[idx] = c;
    g_sin[idx] = s;
}

// ---------------- token-tiled attention with fused RoPE staging ----------------
#define TQ 16
#define UROWS (WW + TQ)   // 144
#define KVP 68
#define PPAD 132
#define A_KS 0
#define A_VS (UROWS*KVP)
#define A_QS (2*UROWS*KVP)
#define A_PS (2*UROWS*KVP + TQ*GG*DD)
#define A_FLOATS (A_PS + TQ*GG*PPAD)
#define ATTN_SMEM (A_FLOATS*4)

__global__ __launch_bounds__(512) void attn_tiled(
    const int* __restrict__ pos, __half* __restrict__ out_hi)
{
    extern __shared__ float sm[];
    float* Ks = sm + A_KS;
    float* Vs = sm + A_VS;
    float* Qs = sm + A_QS;
    float* Ps = sm + A_PS;

    const int khd  = blockIdx.x;
    const int tile = blockIdx.y;
    const int b    = tile >> 6;
    const int i0   = (tile & 63) << 4;
    const int tid  = threadIdx.x;
    const int warp = tid >> 5;
    const int lane = tid & 31;

    // ---- stage K (rope-rotated) + V (plain) ----
    for (int idx = tid; idx < UROWS * 8; idx += 512) {
        int u = idx >> 3, c4 = (idx & 7) * 4;
        int p = i0 - WW + u;
        float4 kl = make_float4(0.f,0.f,0.f,0.f), kh = kl;
        float4 vl = kl, vh = kl;
        if (p >= 0) {
            int t = b * SS + p;
            size_t off = (size_t)t * QKVSZ + QSZ + khd * DD;
            float4 a = *(const float4*)&g_qkv[off + c4];
            float4 bq_ = *(const float4*)&g_qkv[off + c4 + 32];
            vl = *(const float4*)&g_qkv[off + KVSZ + c4];
            vh = *(const float4*)&g_qkv[off + KVSZ + c4 + 32];
            int pv = pos[t];
            float4 c = *(const float4*)&g_cos[pv * 32 + c4];
            float4 s = *(const float4*)&g_sin[pv * 32 + c4];
            kl.x = a.x * c.x - bq_.x * s.x;  kh.x = a.x * s.x + bq_.x * c.x;
            kl.y = a.y * c.y - bq_.y * s.y;  kh.y = a.y * s.y + bq_.y * c.y;
            kl.z = a.z * c.z - bq_.z * s.z;  kh.z = a.z * s.z + bq_.z * c.z;
            kl.w = a.w * c.w - bq_.w * s.w;  kh.w = a.w * s.w + bq_.w * c.w;
        }
        *(float4*)&Ks[u * KVP + c4]      = kl;
        *(float4*)&Ks[u * KVP + c4 + 32] = kh;
        *(float4*)&Vs[u * KVP + c4]      = vl;
        *(float4*)&Vs[u * KVP + c4 + 32] = vh;
    }
    // ---- stage Q (rope-rotated) ----
    for (int idx = tid; idx < TQ * GG * 8; idx += 512) {
        int lt = idx >> 6, g = (idx >> 3) & 7, c4 = (idx & 7) * 4;
        int t = b * SS + i0 + lt;
        size_t off = (size_t)t * QKVSZ + (khd * GG + g) * DD;
        float4 a = *(const float4*)&g_qkv[off + c4];
        float4 bq_ = *(const float4*)&g_qkv[off + c4 + 32];
        int pv = pos[t];
        float4 c = *(const float4*)&g_cos[pv * 32 + c4];
        float4 s = *(const float4*)&g_sin[pv * 32 + c4];
        float4 ql, qh;
        ql.x = a.x * c.x - bq_.x * s.x;  qh.x = a.x * s.x + bq_.x * c.x;
        ql.y = a.y * c.y - bq_.y * s.y;  qh.y = a.y * s.y + bq_.y * c.y;
        ql.z = a.z * c.z - bq_.z * s.z;  qh.z = a.z * s.z + bq_.z * c.z;
        ql.w = a.w * c.w - bq_.w * s.w;  qh.w = a.w * s.w + bq_.w * c.w;
        *(float4*)&Qs[(lt * GG + g) * DD + c4]      = ql;
        *(float4*)&Qs[(lt * GG + g) * DD + c4 + 32] = qh;
    }
    __syncthreads();

    const int lt = warp;
    const int i  = i0 + lt;
    float* prow0 = &Ps[lt * GG * PPAD];

    {
        float acc[GG][4];
        #pragma unroll
        for (int g = 0; g < GG; g++)
            #pragma unroll
            for (int j = 0; j < 4; j++) acc[g][j] = 0.f;

        const float* kbase = &Ks[(lt + lane) * KVP];
        #pragma unroll
        for (int d4 = 0; d4 < DD; d4 += 4) {
            float4 k4[4];
            #pragma unroll
            for (int j = 0; j < 4; j++)
                k4[j] = *(const float4*)&kbase[j * 32 * KVP + d4];
            #pragma unroll
            for (int g = 0; g < GG; g++) {
                float4 q4 = *(const float4*)&Qs[(lt * GG + g) * DD + d4];
                #pragma unroll
                for (int j = 0; j < 4; j++) {
                    acc[g][j] += q4.x * k4[j].x + q4.y * k4[j].y
                               + q4.z * k4[j].z + q4.w * k4[j].w;
                }
            }
        }
        #pragma unroll
        for (int g = 0; g < GG; g++)
            #pragma unroll
            for (int j = 0; j < 4; j++) {
                int w = lane + j * 32;
                int p = i - WW + w;
                prow0[g * PPAD + w] = (p >= 0) ? acc[g][j] * SCALE : -1e30f;
            }
        if (lane < GG) {
            int g = lane;
            const float* kp = &Ks[(lt + WW) * KVP];
            const float* qp = &Qs[(lt * GG + g) * DD];
            float s = 0.f;
            #pragma unroll
            for (int d = 0; d < DD; d++) s += qp[d] * kp[d];
            prow0[g * PPAD + WW] = s * SCALE;
        }
    }
    __syncwarp();

    #pragma unroll
    for (int g = 0; g < GG; g++) {
        float* row = &prow0[g * PPAD];
        float m = -1e30f;
        for (int w = lane; w < 129; w += 32) m = fmaxf(m, row[w]);
        #pragma unroll
        for (int o = 16; o; o >>= 1) m = fmaxf(m, __shfl_xor_sync(0xffffffffu, m, o));
        float sum = 0.f;
        for (int w = lane; w < 129; w += 32) {
            float e = __expf(row[w] - m);
            row[w] = e;
            sum += e;
        }
        #pragma unroll
        for (int o = 16; o; o >>= 1) sum += __shfl_xor_sync(0xffffffffu, sum, o);
        float inv = 1.f / sum;
        for (int w = lane; w < 129; w += 32) row[w] *= inv;
    }
    __syncwarp();

    {
        const int d0 = lane * 2;
        float acc0[GG], acc1[GG];
        #pragma unroll
        for (int g = 0; g < GG; g++) { acc0[g] = 0.f; acc1[g] = 0.f; }

        for (int wb = 0; wb < WW; wb += 4) {
            float2 v2[4];
            #pragma unroll
            for (int j = 0; j < 4; j++)
                v2[j] = *(const float2*)&Vs[(lt + wb + j) * KVP + d0];
            #pragma unroll
            for (int g = 0; g < GG; g++) {
                float4 p4 = *(const float4*)&prow0[g * PPAD + wb];
                acc0[g] += p4.x * v2[0].x + p4.y * v2[1].x + p4.z * v2[2].x + p4.w * v2[3].x;
                acc1[g] += p4.x * v2[0].y + p4.y * v2[1].y + p4.z * v2[2].y + p4.w * v2[3].y;
            }
        }
        {
            float2 v2 = *(const float2*)&Vs[(lt + WW) * KVP + d0];
            #pragma unroll
            for (int g = 0; g < GG; g++) {
                float p = prow0[g * PPAD + WW];
                acc0[g] += p * v2.x;
                acc1[g] += p * v2.y;
            }
        }
        int t = b * SS + i;
        #pragma unroll
        for (int g = 0; g < GG; g++) {
            __half2 h2 = __floats2half2_rn(acc0[g], acc1[g]);
            *(__half2*)&out_hi[((size_t)t * HQ + khd * GG + g) * DD + d0] = h2;
        }
    }
}

// ---------------- launch ----------------
extern "C" void kernel_launch(void* const* d_in, const int* in_sizes, int n_in,
                              void* d_out, int out_size)
{
    const float* hs = (const float*)d_in[0];
    const int*  pos = (const int*)  d_in[1];
    const float* Wq = (const float*)d_in[2];
    const float* bq = (const float*)d_in[3];
    const float* Wk = (const float*)d_in[4];
    const float* bk = (const float*)d_in[5];
    const float* Wv = (const float*)d_in[6];
    const float* bv = (const float*)d_in[7];
    const float* Wo = (const float*)d_in[8];
    const float* bo = (const float*)d_in[9];
    float* out = (float*)d_out;

    __half *hs_hi, *wqkv_hi, *wo_hi, *att_hi;
    float *bqkv, *qkv;
    cudaGetSymbolAddress((void**)&hs_hi,   g_hs_hi);
    cudaGetSymbolAddress((void**)&wqkv_hi, g_Wqkv_hi);
    cudaGetSymbolAddress((void**)&bqkv,    g_bqkv);
    cudaGetSymbolAddress((void**)&qkv,     g_qkv);
    cudaGetSymbolAddress((void**)&wo_hi,   g_Wo_hi);
    cudaGetSymbolAddress((void**)&att_hi,  g_att_hi);

    cudaFuncSetAttribute(gemm_f16single, cudaFuncAttributeMaxDynamicSharedMemorySize, GEMM1_SMEM);
    cudaFuncSetAttribute(attn_tiled, cudaFuncAttributeMaxDynamicSharedMemorySize, ATTN_SMEM);

    // (0) combined bias
    concat_bias<<<(QKVSZ + 255) / 256, 256>>>(bq, bk, bv, bqkv);
    // (1) hidden_states -> fp16 hi
    {
        int n4 = TT * HID / 4;
        convert_hi<<<(n4 + 255) / 256, 256>>>(hs, hs_hi, n4);
    }
    // (2) fused QKV weight transpose (hi only)
    {
        dim3 blk(32, 8);
        cts_qkv_hi<<<dim3(QKVSZ / 32, HID / 32), blk>>>(Wq, Wk, Wv, wqkv_hi);
    }
    // (3) fused QKV projection (512 threads, 32 warps/SM)  <-- profiled slot
    gemm_f16single<<<dim3(QKVSZ / 128, TT / 128), 512, GEMM1_SMEM>>>(
        hs_hi, wqkv_hi, bqkv, qkv, TT, QKVSZ, HID, OSCALE);
    // (4) rope cos/sin table
    rope_table<<<(SS * 32 + 255) / 256, 256>>>();
    // (5) Wo transpose (hi only)
    {
        dim3 blk(32, 8);
        cts_wo_hi<<<dim3(HID / 32, QSZ / 32), blk>>>(Wo, wo_hi);
    }
    // (6) attention with fused RoPE staging
    {
        dim3 ga(HKV, TT / TQ);
        attn_tiled<<<ga, 512, ATTN_SMEM>>>(pos, att_hi);
    }
    // (7) output projection (512 threads)
    gemm_f16single<<<dim3((HID + 127) / 128, TT / 128), 512, GEMM1_SMEM>>>(
        att_hi, wo_hi, bo, out, TT, HID, QSZ, OSCALE);
}